// round 10
// baseline (speedup 1.0000x reference)
#include <cuda_runtime.h>

// Problem constants
#define Cdim   16
#define CIN    18          // C + 2 (x_rel, y_rel)
#define Hh     128
#define Ww     128
#define HW     (Hh*Ww)     // 16384
#define Bb     4
#define Oo     32
#define BO     (Bb*Oo)     // 128
#define WTOT   593         // (C+2)*C + C + C*C + C + C + 1
#define TILES  32          // HW / PIXB
#define PIXB   512         // pixels per block
#define THREADS 128        // 4 pixels per thread
#define NB     (Bb*Oo*TILES)  // 4096 partials

// Compact reordered weights: one 640-float row per (b,o), final smem layout.
//  [0)    w1f[c*16+k]            288 floats
//  [288)  w2f[k*16+c]            256 floats
//  [544)  b1 (natural pairs)      16 floats
//  [560)  (b2_k, 0) pairs         32 floats
//  [592)  w3                      16 floats
//  [608)  b3                       1 float   (row padded to 640)
#define WROW   640
#define OFF_W1 0
#define OFF_W2 288
#define OFF_B1 544
#define OFF_B2 560
#define OFF_W3 592
#define OFF_B3 608

__device__ __align__(16) float g_w[BO * WROW];
// Deterministic partial sums: layout [3 quantities][Bb][1024 per-b partials]
__device__ __align__(16) float g_part[3*NB];

// ---------------- packed f32x2 helpers ----------------
__device__ __forceinline__ unsigned long long pack2f(float lo, float hi) {
    unsigned long long d;
    asm("mov.b64 %0, {%1, %2};" : "=l"(d)
        : "r"(__float_as_uint(lo)), "r"(__float_as_uint(hi)));
    return d;
}
__device__ __forceinline__ void unpack2f(unsigned long long v, float& lo, float& hi) {
    unsigned int a, b;
    asm("mov.b64 {%0, %1}, %2;" : "=r"(a), "=r"(b) : "l"(v));
    lo = __uint_as_float(a); hi = __uint_as_float(b);
}
__device__ __forceinline__ unsigned long long fma2(unsigned long long a,
                                                   unsigned long long b,
                                                   unsigned long long c) {
    unsigned long long d;
    asm("fma.rn.f32x2 %0, %1, %2, %3;" : "=l"(d) : "l"(a), "l"(b), "l"(c));
    return d;
}
__device__ __forceinline__ unsigned long long relu2(unsigned long long v) {
    float a, b; unpack2f(v, a, b);
    return pack2f(fmaxf(a, 0.0f), fmaxf(b, 0.0f));
}
__device__ __forceinline__ float warpRed(float v) {
    v += __shfl_xor_sync(0xffffffffu, v, 16);
    v += __shfl_xor_sync(0xffffffffu, v, 8);
    v += __shfl_xor_sync(0xffffffffu, v, 4);
    v += __shfl_xor_sync(0xffffffffu, v, 2);
    v += __shfl_xor_sync(0xffffffffu, v, 1);
    return v;
}

// ---------------- pre-gather: one thread per weight element (1 DRAM round) ----------------
#define GTHREADS 640
__global__ __launch_bounds__(GTHREADS)
void gather_weights_kernel(const float* __restrict__ cw,
                           const int*   __restrict__ mask,
                           const int*   __restrict__ ind) {
    const int bo = blockIdx.x;
    if (mask[bo] == 0) return;                 // unused by main kernel
    const int i = threadIdx.x;
    if (i >= WTOT) return;
    const int b   = bo >> 5;
    const int pos = ind[bo];
    float* dst = g_w + bo * WROW;

    float w = cw[((long)b*WTOT + i)*HW + pos];
    if (i < 288) {                         // w1[k][c] -> [c*16+k]
        int k = i / CIN, c = i % CIN;
        dst[OFF_W1 + c*16 + k] = w;
    } else if (i < 304) {                  // b1 natural
        dst[OFF_B1 + (i - 288)] = w;
    } else if (i < 560) {                  // w2[k][c] -> [k*16+c]
        int j = i - 304; int k = j >> 4, c = j & 15;
        dst[OFF_W2 + k*16 + c] = w;
    } else if (i < 576) {                  // b2 -> (b2_k, 0)
        int k = i - 560;
        dst[OFF_B2 + 2*k]     = w;
        dst[OFF_B2 + 2*k + 1] = 0.0f;
    } else if (i < 592) {                  // w3
        dst[OFF_W3 + (i - 576)] = w;
    } else {                               // b3
        dst[OFF_B3] = w;
    }
}

// ---------------- main MLP + dice-accumulate kernel ----------------
// k-pair packing: f32x2 lanes hold (out_k, out_k+1) per pixel; weights natural.
__global__ __launch_bounds__(THREADS, 4)
void dice_mlp_kernel(const float* __restrict__ seg,
                     const int*   __restrict__ mask,
                     const int*   __restrict__ ind,
                     const float* __restrict__ tgt) {
    const int bo   = blockIdx.x;           // b*Oo + o
    const int tile = blockIdx.y;
    const int b    = bo >> 5;
    const int tid  = threadIdx.x;
    // partial index within batch b: tile*32 + o  -> g_part layout [q][b][1024]
    const int bid  = b*1024 + tile*Oo + (bo & 31);

    // Masked-out (b,o): contributes nothing (pred*mask, tgt*mask both zero).
    if (mask[bo] == 0) {
        if (tid == 0) {
            g_part[bid]        = 0.0f;
            g_part[NB  + bid]  = 0.0f;
            g_part[2*NB + bid] = 0.0f;
        }
        return;
    }

    __shared__ __align__(16) float s_wbuf[WROW];
    __shared__ float s_red[12];

    {   // coalesced L2-hit copy of prepacked weights (160 float4)
        const float4* src = (const float4*)(g_w + bo * WROW);
        float4*       dst = (float4*)s_wbuf;
#pragma unroll
        for (int i = 0; i < 2; i++) {
            int idx = tid + i*THREADS;
            if (idx < WROW/4) dst[idx] = src[idx];
        }
    }
    __syncthreads();

    const int pos = ind[bo];

    // This thread's 4 pixels (consecutive -> float4 loads, same row)
    const int p0 = tile*PIXB + tid*4;
    const int px = p0 & (Ww - 1);
    const int py = p0 >> 7;
    const float xi = (float)(pos & (Ww - 1));
    const float yi = (float)(pos >> 7);
    const float inv = 1.0f / 128.0f;
    const float xr0 = ((float)px - xi) * inv;
    const float yr  = ((float)py - yi) * inv;

    const ulonglong2* w1u = (const ulonglong2*)(s_wbuf + OFF_W1);  // [c][j]
    const ulonglong2* w2u = (const ulonglong2*)(s_wbuf + OFF_W2);  // [k][j]
    const unsigned long long* s_b1p = (const unsigned long long*)(s_wbuf + OFF_B1);
    const unsigned long long* s_b2p = (const unsigned long long*)(s_wbuf + OFF_B2);
    const float* s_w3 = s_wbuf + OFF_W3;
    const float  b3   = s_wbuf[OFF_B3];

    // ---- layer 1: 18 -> 16.  acc[p][j] = (h_2j, h_2j+1) for pixel p ----
    unsigned long long acc[4][8];
#pragma unroll
    for (int p = 0; p < 4; p++)
#pragma unroll
        for (int j = 0; j < 8; j++) acc[p][j] = s_b1p[j];

    const float* segb = seg + (long)b*Cdim*HW + p0;
    float4 fcur = *(const float4*)(segb);
    for (int c = 0; c < Cdim; c++) {
        float4 f = fcur;
        if (c + 1 < Cdim) fcur = *(const float4*)(segb + (c + 1)*HW);  // prefetch
        unsigned long long fp[4];
        fp[0] = pack2f(f.x, f.x);
        fp[1] = pack2f(f.y, f.y);
        fp[2] = pack2f(f.z, f.z);
        fp[3] = pack2f(f.w, f.w);
#pragma unroll
        for (int j = 0; j < 4; j++) {
            ulonglong2 wv = w1u[c*4 + j];
#pragma unroll
            for (int p = 0; p < 4; p++) {
                acc[p][2*j]     = fma2(wv.x, fp[p], acc[p][2*j]);
                acc[p][2*j + 1] = fma2(wv.y, fp[p], acc[p][2*j + 1]);
            }
        }
    }
    {   // c = 16: x_rel (distinct per pixel)
        unsigned long long fp[4];
#pragma unroll
        for (int p = 0; p < 4; p++) {
            float xr = xr0 + (float)p * inv;
            fp[p] = pack2f(xr, xr);
        }
#pragma unroll
        for (int j = 0; j < 4; j++) {
            ulonglong2 wv = w1u[16*4 + j];
#pragma unroll
            for (int p = 0; p < 4; p++) {
                acc[p][2*j]     = fma2(wv.x, fp[p], acc[p][2*j]);
                acc[p][2*j + 1] = fma2(wv.y, fp[p], acc[p][2*j + 1]);
            }
        }
    }
    {   // c = 17: y_rel (same for all 4 pixels)
        unsigned long long fy = pack2f(yr, yr);
#pragma unroll
        for (int j = 0; j < 4; j++) {
            ulonglong2 wv = w1u[17*4 + j];
#pragma unroll
            for (int p = 0; p < 4; p++) {
                acc[p][2*j]     = fma2(wv.x, fy, acc[p][2*j]);
                acc[p][2*j + 1] = fma2(wv.y, fy, acc[p][2*j + 1]);
            }
        }
    }

    // relu in place: acc becomes h1 (pairs over c for layer 2)
#pragma unroll
    for (int p = 0; p < 4; p++)
#pragma unroll
        for (int j = 0; j < 8; j++) acc[p][j] = relu2(acc[p][j]);

    // ---- layer 2 (16 -> 16) + layer 3 (16 -> 1) fused, pairwise over c ----
    float z[4];
#pragma unroll
    for (int p = 0; p < 4; p++) z[p] = b3;

#pragma unroll 4
    for (int k = 0; k < 16; k++) {
        unsigned long long a2[4];
#pragma unroll
        for (int p = 0; p < 4; p++) a2[p] = s_b2p[k];   // (b2_k, 0)
#pragma unroll
        for (int j = 0; j < 4; j++) {
            ulonglong2 wv = w2u[k*4 + j];
#pragma unroll
            for (int p = 0; p < 4; p++) {
                a2[p] = fma2(wv.x, acc[p][2*j],     a2[p]);
                a2[p] = fma2(wv.y, acc[p][2*j + 1], a2[p]);
            }
        }
        float w3k = s_w3[k];
#pragma unroll
        for (int p = 0; p < 4; p++) {
            float lo, hi; unpack2f(a2[p], lo, hi);
            float h2 = fmaxf(lo + hi, 0.0f);
            z[p] = fmaf(w3k, h2, z[p]);
        }
    }

    // ---- sigmoid + dice partials ----
    float pr0 = 1.0f / (1.0f + __expf(-z[0]));
    float pr1 = 1.0f / (1.0f + __expf(-z[1]));
    float pr2 = 1.0f / (1.0f + __expf(-z[2]));
    float pr3 = 1.0f / (1.0f + __expf(-z[3]));

    float4 t = *(const float4*)(tgt + (long)bo*HW + p0);

    float ai = pr0*t.x + pr1*t.y + pr2*t.z + pr3*t.w;
    float ap = pr0*pr0 + pr1*pr1 + pr2*pr2 + pr3*pr3;
    float at = t.x*t.x + t.y*t.y + t.z*t.z + t.w*t.w;

    // Block reduction (128 threads = 4 warps)
    ai = warpRed(ai); ap = warpRed(ap); at = warpRed(at);
    int wid = tid >> 5, lane = tid & 31;
    if (lane == 0) { s_red[wid] = ai; s_red[4 + wid] = ap; s_red[8 + wid] = at; }
    __syncthreads();
    if (tid == 0) {
        float I = s_red[0] + s_red[1] + s_red[2] + s_red[3];
        float P = s_red[4] + s_red[5] + s_red[6] + s_red[7];
        float T = s_red[8] + s_red[9] + s_red[10] + s_red[11];
        g_part[bid]        = I;
        g_part[NB  + bid]  = P;
        g_part[2*NB + bid] = T;
    }
}

// ---------------- deterministic finalize: 24 warps, two per (quantity,batch) ----------------
__global__ __launch_bounds__(768)
void dice_finalize_kernel(float* __restrict__ out) {
    __shared__ float s[24];
    const int w    = threadIdx.x >> 5;   // 0..23 == (q*4+b)*2 + half
    const int lane = threadIdx.x & 31;
    const int arr  = w >> 1;             // 0..11
    const int half = w & 1;

    const float4* p4 = (const float4*)&g_part[arr * 1024 + half * 512];
    float v = 0.0f;
#pragma unroll
    for (int i = 0; i < 4; i++) {
        float4 f = p4[lane + 32*i];
        v += (f.x + f.y) + (f.z + f.w);
    }
    v = warpRed(v);
    if (lane == 0) s[w] = v;
    __syncthreads();

    if (threadIdx.x == 0) {
        float loss = 0.0f;
#pragma unroll
        for (int b = 0; b < Bb; b++) {
            float I = s[2*b]          + s[2*b + 1];
            float P = s[2*(4 + b)]    + s[2*(4 + b) + 1];
            float T = s[2*(8 + b)]    + s[2*(8 + b) + 1];
            loss += 1.0f - (2.0f*I + 1.0f) / (P + T + 1.0f);
        }
        out[0] = loss * 0.25f;
    }
}

extern "C" void kernel_launch(void* const* d_in, const int* in_sizes, int n_in,
                              void* d_out, int out_size) {
    const float* seg  = (const float*)d_in[0];
    const float* cw   = (const float*)d_in[1];
    const int*   mask = (const int*)  d_in[2];
    const int*   ind  = (const int*)  d_in[3];
    const float* tgt  = (const float*)d_in[4];

    gather_weights_kernel<<<BO, GTHREADS>>>(cw, mask, ind);
    dim3 grid(BO, TILES);   // bo fast -> masked/unmasked interleaved per wave
    dice_mlp_kernel<<<grid, THREADS>>>(seg, mask, ind, tgt);
    dice_finalize_kernel<<<1, 768>>>((float*)d_out);
}